// round 3
// baseline (speedup 1.0000x reference)
#include <cuda_runtime.h>
#include <cuda_bf16.h>
#include <cstdint>

#define NGROUP 1024
#define MAXB   64
#define TSLAB  64     // tokens per slab CTA

// Per-batch group start offsets (sentinel at NGROUP = S)
__device__ int g_start_g[MAXB * (NGROUP + 1)];

// ---------------------------------------------------------------------------
// Kernel A: per-group binary searches -> g_start table + counts; zero-init
// output rows for empty groups and groups spanning a slab boundary.
// grid = (NGROUP/128, B), 128 threads.
// ---------------------------------------------------------------------------
__global__ __launch_bounds__(128)
void prep_kernel(const int* __restrict__ seg,
                 float4* __restrict__ out,
                 float*  __restrict__ counts_out,
                 int S, int Hv) {
    __shared__ int st[130];
    __shared__ int zlist[129];
    __shared__ int zn;

    const int b   = blockIdx.y;
    const int g0  = blockIdx.x * 128;
    const int tid = threadIdx.x;
    const int* row = seg + (size_t)b * S;

    if (tid == 0) zn = 0;

    // lower_bound for g0+tid
    {
        int target = g0 + tid;
        int lo = 0, hi = S;
        while (lo < hi) { int m = (lo + hi) >> 1; if (row[m] < target) lo = m + 1; else hi = m; }
        st[tid] = lo;
    }
    if (tid == 0) {
        int target = g0 + 128;   // one extra boundary
        int lo = 0, hi = S;
        while (lo < hi) { int m = (lo + hi) >> 1; if (row[m] < target) lo = m + 1; else hi = m; }
        st[128] = lo;
    }
    __syncthreads();

    const int g  = g0 + tid;
    const int gs = st[tid];
    const int ge = st[tid + 1];
    const int cnt = ge - gs;

    g_start_g[b * (NGROUP + 1) + g] = gs;
    if (tid == 0) g_start_g[b * (NGROUP + 1) + g0 + 128] = st[128];

    if (counts_out != nullptr)
        counts_out[(size_t)b * NGROUP + g] = (float)cnt;

    // needs zero-init: empty group, or group spanning a slab boundary
    bool needZero = (cnt == 0) || ((gs / TSLAB) != ((ge - 1) / TSLAB));
    if (needZero) {
        int i = atomicAdd(&zn, 1);
        zlist[i] = g;
    }
    __syncthreads();

    const int n = zn;
    const float4 z = {0.f, 0.f, 0.f, 0.f};
    for (int i = 0; i < n; ++i) {
        float4* o = out + ((size_t)b * NGROUP + zlist[i]) * Hv;
        for (int v = tid; v < Hv; v += 128) o[v] = z;
    }
}

// ---------------------------------------------------------------------------
// Kernel B: one CTA per 64-token slab. Streams its contiguous slab of feats,
// segmented-reduces by group. Interior groups: plain scaled store.
// Slab-spanning groups: atomicAdd of the scaled partial (pre-zeroed).
// grid = (S/TSLAB, B), 128 threads.
// ---------------------------------------------------------------------------
__global__ __launch_bounds__(128)
void slab_pool_kernel(const float4* __restrict__ feats,
                      const int*   __restrict__ seg,
                      float4*      __restrict__ out,
                      int S, int Hv) {
    __shared__ int seg_sh[TSLAB];

    const int b   = blockIdx.y;
    const int t0  = blockIdx.x * TSLAB;
    const int t1  = min(t0 + TSLAB, S);
    const int tid = threadIdx.x;

    const int* row = seg + (size_t)b * S;
    if (tid < t1 - t0) seg_sh[tid] = row[t0 + tid];
    __syncthreads();

    const int* gst = g_start_g + b * (NGROUP + 1);
    const float4* fbase = feats + (size_t)b * S * Hv;
    float4* obase = out + (size_t)b * NGROUP * Hv;

    for (int v = tid; v < Hv; v += 128) {
        int t = t0;
        while (t < t1) {
            const int g  = seg_sh[t - t0];
            const int gs = __ldg(&gst[g]);
            const int ge = __ldg(&gst[g + 1]);
            const int e  = min(ge, t1);

            float ax = 0.f, ay = 0.f, az = 0.f, aw = 0.f;
            const float4* p = fbase + v;
            #pragma unroll 4
            for (int tt = t; tt < e; ++tt) {
                float4 x = __ldg(p + (size_t)tt * Hv);
                ax += x.x; ay += x.y; az += x.z; aw += x.w;
            }

            const float inv = 1.0f / (float)(ge - gs);
            float4* o = obase + (size_t)g * Hv + v;
            if (gs >= t0 && ge <= t1) {
                float4 r; r.x = ax * inv; r.y = ay * inv; r.z = az * inv; r.w = aw * inv;
                *o = r;
            } else {
                float* of = (float*)o;
                atomicAdd(of + 0, ax * inv);
                atomicAdd(of + 1, ay * inv);
                atomicAdd(of + 2, az * inv);
                atomicAdd(of + 3, aw * inv);
            }
            t = e;
        }
    }
}

// ---------------------------------------------------------------------------
extern "C" void kernel_launch(void* const* d_in, const int* in_sizes, int n_in,
                              void* d_out, int out_size) {
    const float* feats = (const float*)d_in[0];
    const int*   seg   = (const int*)d_in[1];
    float* out = (float*)d_out;

    const int n_feat = in_sizes[0];   // B*S*H
    const int n_seg  = in_sizes[1];   // B*S
    const int H = n_feat / n_seg;

    int B;
    bool has_counts;
    if (out_size % (NGROUP * (H + 1)) == 0) {
        B = out_size / (NGROUP * (H + 1));
        has_counts = true;
        if (B <= 0 || n_seg % B != 0) {
            B = out_size / (NGROUP * H);
            has_counts = false;
        }
    } else {
        B = out_size / (NGROUP * H);
        has_counts = false;
    }
    const int S = n_seg / B;
    const int Hv = H / 4;

    float* counts_out = has_counts ? out + (size_t)B * NGROUP * H : nullptr;

    // Kernel A: boundaries + counts + zero-init of atomic targets
    {
        dim3 grid(NGROUP / 128, B);
        prep_kernel<<<grid, 128>>>(seg, (float4*)out, counts_out, S, Hv);
    }

    // Kernel B: slab-stationary pooling
    {
        dim3 grid((S + TSLAB - 1) / TSLAB, B);
        slab_pool_kernel<<<grid, 128>>>((const float4*)feats, seg,
                                        (float4*)out, S, Hv);
    }
}